// round 5
// baseline (speedup 1.0000x reference)
#include <cuda_runtime.h>
#include <cuda_bf16.h>
#include <cstdint>

// ---------------- problem constants ----------------
#define B       8
#define N       4096
#define S       1024          // NPOINT
#define NS      32            // NSAMPLE
#define CIN     64
#define CMLP    128
#define COUT    256
#define BN_EPS  1e-5f
#define M_TOT   (B*S*NS)      // 262144 samples per channel for BN

// ---------------- f32x2 helpers (GEMM only — NOT bit-exact-critical paths) ----
#define SPLAT2(d, v)       asm("mov.b64 %0, {%1,%1};" : "=l"(d) : "f"(v))
#define UNPACK2(lo, hi, d) asm("mov.b64 {%0,%1}, %2;" : "=f"(lo), "=f"(hi) : "l"(d))
#define FMA2(acc, a, b)    asm("fma.rn.f32x2 %0, %1, %2, %0;" : "+l"(acc) : "l"(a), "l"(b))

// ---------------- device scratch (no allocs allowed) ----------------
__device__ float4 g_cent[B * S];                       // FPS centroids (new_xyz)
__device__ float  g_feats[(size_t)B * N * CMLP];       // points @ W1 + b1   (16 MB)
__device__ int    g_gidx[B * S * NS];                  // ball query indices (1 MB)
__device__ float  g_sum[COUT];
__device__ float  g_sumsq[COUT];

// ---------------- kernel: zero BN stats ----------------
__global__ void zero_stats_kernel() {
    g_sum[threadIdx.x] = 0.f;
    g_sumsq[threadIdx.x] = 0.f;
}

// ---------------- kernel: farthest point sampling ----------------
// EXACT round-2 version (known bit-correct vs XLA). One block per batch,
// 512 threads, 8 points per thread. Scalar rn ops only — no packed math.
//   d = ((dx*dx) + (dy*dy)) + (dz*dz)
__global__ __launch_bounds__(512) void fps_kernel(const float* __restrict__ xyz) {
    const int b = blockIdx.x;
    const float* X = xyz + (size_t)b * N * 3;
    const int tid = threadIdx.x;
    const int lane = tid & 31, wid = tid >> 5;

    float px[8], py[8], pz[8], dmin[8];
#pragma unroll
    for (int j = 0; j < 8; j++) {
        int p = tid + j * 512;
        px[j] = X[p * 3 + 0];
        py[j] = X[p * 3 + 1];
        pz[j] = X[p * 3 + 2];
        dmin[j] = 1e10f;
    }

    __shared__ float s_wv[16];
    __shared__ int   s_wi[16];
    __shared__ int   s_far;
    __shared__ float s_c[3];
    if (tid == 0) s_far = 0;
    __syncthreads();

    for (int it = 0; it < S; it++) {
        if (tid == 0) {
            int f = s_far;
            float cx = X[f * 3 + 0], cy = X[f * 3 + 1], cz = X[f * 3 + 2];
            s_c[0] = cx; s_c[1] = cy; s_c[2] = cz;
            g_cent[b * S + it] = make_float4(cx, cy, cz, 0.f);
        }
        __syncthreads();
        const float cx = s_c[0], cy = s_c[1], cz = s_c[2];

        float bv = -1.f;  int bi = 0x7fffffff;
#pragma unroll
        for (int j = 0; j < 8; j++) {
            float dx = __fsub_rn(px[j], cx);
            float dy = __fsub_rn(py[j], cy);
            float dz = __fsub_rn(pz[j], cz);
            float d  = __fadd_rn(__fadd_rn(__fmul_rn(dx, dx), __fmul_rn(dy, dy)),
                                 __fmul_rn(dz, dz));
            float dm = fminf(dmin[j], d);
            dmin[j] = dm;
            if (dm > bv) { bv = dm; bi = tid + j * 512; }   // strict > keeps lowest index
        }
        // warp argmax reduce (tie -> lowest index, matching jnp.argmax)
#pragma unroll
        for (int o = 16; o > 0; o >>= 1) {
            float ov = __shfl_down_sync(0xffffffffu, bv, o);
            int   oi = __shfl_down_sync(0xffffffffu, bi, o);
            if (ov > bv || (ov == bv && oi < bi)) { bv = ov; bi = oi; }
        }
        if (lane == 0) { s_wv[wid] = bv; s_wi[wid] = bi; }
        __syncthreads();
        if (wid == 0) {
            float v = (lane < 16) ? s_wv[lane] : -2.f;
            int   i = (lane < 16) ? s_wi[lane] : 0x7fffffff;
#pragma unroll
            for (int o = 16; o > 0; o >>= 1) {
                float ov = __shfl_down_sync(0xffffffffu, v, o);
                int   oi = __shfl_down_sync(0xffffffffu, i, o);
                if (ov > v || (ov == v && oi < i)) { v = ov; i = oi; }
            }
            if (lane == 0) s_far = i;    // same thread (tid 0) reads it next iter
        }
    }
}

// ---------------- kernel: feats = points @ W1 + b1 ----------------
// block: 64 rows x 128 cols, K=64.  grid (64, 8), 256 threads.
__global__ __launch_bounds__(256) void feats_kernel(const float* __restrict__ points,
                                                    const float* __restrict__ W1,
                                                    const float* __restrict__ b1) {
    __shared__ float Ps[CIN * 68];        // k-major, padded: Ps[k*68 + r], r<64
    __shared__ float Ws[32 * CMLP];       // K-chunk of 32: Ws[k*128 + c]

    const int b  = blockIdx.y;
    const int r0 = blockIdx.x * 64;
    const int t  = threadIdx.x;
    const int tx = t & 15;                // 8 cols each
    const int ty = t >> 4;                // 4 rows each

    for (int i = t; i < 64 * CIN; i += 256) {
        int r = i >> 6, k = i & 63;
        Ps[k * 68 + r] = points[((size_t)b * N + r0 + r) * CIN + k];
    }

    float acc[4][8];
#pragma unroll
    for (int i = 0; i < 4; i++)
#pragma unroll
        for (int j = 0; j < 8; j++) acc[i][j] = 0.f;

    for (int kk = 0; kk < CIN; kk += 32) {
        __syncthreads();
#pragma unroll
        for (int i = 0; i < 16; i++)
            Ws[(i * 2 + (t >> 7)) * CMLP + (t & 127)] =
                W1[(kk + i * 2 + (t >> 7)) * CMLP + (t & 127)];
        __syncthreads();
#pragma unroll
        for (int k = 0; k < 32; k++) {
            float a[4], w[8];
            const float* ps = Ps + (kk + k) * 68 + ty * 4;
#pragma unroll
            for (int i = 0; i < 4; i++) a[i] = ps[i];
            const float* ws = Ws + k * CMLP + tx * 8;
#pragma unroll
            for (int j = 0; j < 8; j++) w[j] = ws[j];
#pragma unroll
            for (int i = 0; i < 4; i++)
#pragma unroll
                for (int j = 0; j < 8; j++) acc[i][j] += a[i] * w[j];
        }
    }

    float bias[8];
#pragma unroll
    for (int j = 0; j < 8; j++) bias[j] = b1[tx * 8 + j];
#pragma unroll
    for (int i = 0; i < 4; i++) {
        size_t row = (size_t)b * N + r0 + ty * 4 + i;
        float* o = g_feats + row * CMLP + tx * 8;
#pragma unroll
        for (int j = 0; j < 8; j++) o[j] = acc[i][j] + bias[j];
    }
}

// ---------------- kernel: ball query ----------------
// 512 threads = 16 warps = 16 centroids per block; xyz tile staged in smem (SoA).
__global__ __launch_bounds__(512) void ballq_kernel(const float* __restrict__ xyz) {
    __shared__ float sx[N], sy[N], sz[N];     // 48 KB

    const float R2 = (float)(0.15 * 0.15);    // f64 product cast to f32, matching JAX
    const int tid  = threadIdx.x;
    const int w    = blockIdx.x * 16 + (tid >> 5);
    const int lane = tid & 31;
    const int b    = w >> 10;                 // 64 blocks per batch (16 | 1024)
    const float* X = xyz + (size_t)b * N * 3;

    // cooperative SoA load of this batch's xyz
    for (int idx = tid; idx < N * 3; idx += 512) {
        float f = X[idx];
        int p = idx / 3, c = idx - p * 3;
        if (c == 0) sx[p] = f; else if (c == 1) sy[p] = f; else sz[p] = f;
    }
    __syncthreads();

    float4 cc = g_cent[w];
    int count = 0;
    int first = -1;
    int* out = g_gidx + w * NS;

    for (int c0 = 0; c0 < N; c0 += 32) {
        int p = c0 + lane;
        float dx = __fsub_rn(sx[p], cc.x);
        float dy = __fsub_rn(sy[p], cc.y);
        float dz = __fsub_rn(sz[p], cc.z);
        float d = __fadd_rn(__fadd_rn(__fmul_rn(dx, dx), __fmul_rn(dy, dy)),
                            __fmul_rn(dz, dz));
        bool ok = !(d > R2);
        unsigned m = __ballot_sync(0xffffffffu, ok);
        if (count == 0 && m) first = c0 + __ffs(m) - 1;
        int pos = count + __popc(m & ((1u << lane) - 1));
        if (ok && pos < NS) out[pos] = p;
        count += __popc(m);
        if (count >= NS) break;     // warp-uniform (count derived from ballot)
    }
    for (int i = count + lane; i < NS; i += 32) out[i] = first;
}

// ---------------- kernel: gather-GEMM + BN stats + maxpool ----------------
// one block per (b,s): h(32x256) = feats[gidx] (32x128) @ Wc + bc.
// 256 threads; per-thread tile 4 rows x 8 cols (acc as 16 f32x2 over col pairs).
__global__ __launch_bounds__(256) void group_gemm_kernel(const float* __restrict__ Wc,
                                                         const float* __restrict__ bc,
                                                         float* __restrict__ out) {
    __shared__ float As[CMLP * 32];    // k-major: As[k*32 + r]   (16 KB)
    __shared__ float Ws[32 * COUT];    // K-chunk of 32: Ws[k*256+c] (32 KB)

    const int bs = blockIdx.x;
    const int b  = bs >> 10;
    const int t  = threadIdx.x;

    // gather A: r = t%32, k-range = (t/32)*16 .. +15
    {
        const int r  = t & 31;
        const int kb = (t >> 5) * 16;
        const int row = g_gidx[bs * NS + r];
        const float* fr = g_feats + ((size_t)b * N + row) * CMLP + kb;
#pragma unroll
        for (int i = 0; i < 16; i += 4) {
            float4 v = *(const float4*)(fr + i);
            As[(kb + i + 0) * 32 + r] = v.x;
            As[(kb + i + 1) * 32 + r] = v.y;
            As[(kb + i + 2) * 32 + r] = v.z;
            As[(kb + i + 3) * 32 + r] = v.w;
        }
    }

    const int tr = (t & 7) * 4;        // row group (4 rows)
    const int tc = (t >> 3) * 8;       // col group (8 cols)

    unsigned long long acc[4][4];      // [row][colpair]
#pragma unroll
    for (int i = 0; i < 4; i++)
#pragma unroll
        for (int j = 0; j < 4; j++) acc[i][j] = 0ull;

    for (int kk = 0; kk < CMLP; kk += 32) {
        __syncthreads();
        {   // load Ws chunk (32x256 floats) as float4, 8 per thread
            const float4* src = (const float4*)(Wc + kk * COUT);
            float4* dst = (float4*)Ws;
#pragma unroll
            for (int i = 0; i < 8; i++) dst[t + i * 256] = src[t + i * 256];
        }
        __syncthreads();
#pragma unroll
        for (int k = 0; k < 32; k++) {
            // FIX (round 4 bug): A must be indexed by GLOBAL k = kk + k.
            float4 a4 = *(const float4*)(As + (kk + k) * 32 + tr);
            ulonglong2 wq0 = *(const ulonglong2*)(Ws + k * COUT + tc);
            ulonglong2 wq1 = *(const ulonglong2*)(Ws + k * COUT + tc + 4);
            unsigned long long wp0 = wq0.x, wp1 = wq0.y, wp2 = wq1.x, wp3 = wq1.y;
            unsigned long long a0, a1, a2, a3;
            SPLAT2(a0, a4.x); SPLAT2(a1, a4.y); SPLAT2(a2, a4.z); SPLAT2(a3, a4.w);
            FMA2(acc[0][0], a0, wp0); FMA2(acc[0][1], a0, wp1);
            FMA2(acc[0][2], a0, wp2); FMA2(acc[0][3], a0, wp3);
            FMA2(acc[1][0], a1, wp0); FMA2(acc[1][1], a1, wp1);
            FMA2(acc[1][2], a1, wp2); FMA2(acc[1][3], a1, wp3);
            FMA2(acc[2][0], a2, wp0); FMA2(acc[2][1], a2, wp1);
            FMA2(acc[2][2], a2, wp2); FMA2(acc[2][3], a2, wp3);
            FMA2(acc[3][0], a3, wp0); FMA2(acc[3][1], a3, wp1);
            FMA2(acc[3][2], a3, wp2); FMA2(acc[3][3], a3, wp3);
        }
    }

    // epilogue: bias, per-col stats over the 4 local rows, then reduce over the
    // 8-thread row-group (lanes sharing t>>3) via shfl.xor 1,2,4.
    float bias[8];
    *(float4*)(bias)     = *(const float4*)(bc + tc);
    *(float4*)(bias + 4) = *(const float4*)(bc + tc + 4);

    float m[8], sm[8], sq[8];
#pragma unroll
    for (int cj = 0; cj < 4; cj++) {
        float lo[4], hi[4];
#pragma unroll
        for (int ri = 0; ri < 4; ri++) UNPACK2(lo[ri], hi[ri], acc[ri][cj]);
#pragma unroll
        for (int h = 0; h < 2; h++) {
            int jj = cj * 2 + h;
            float x0 = (h ? hi[0] : lo[0]) + bias[jj];
            float x1 = (h ? hi[1] : lo[1]) + bias[jj];
            float x2 = (h ? hi[2] : lo[2]) + bias[jj];
            float x3 = (h ? hi[3] : lo[3]) + bias[jj];
            m[jj]  = fmaxf(fmaxf(x0, x1), fmaxf(x2, x3));
            sm[jj] = (x0 + x1) + (x2 + x3);
            sq[jj] = (x0 * x0 + x1 * x1) + (x2 * x2 + x3 * x3);
        }
    }
#pragma unroll
    for (int off = 1; off < 8; off <<= 1) {
#pragma unroll
        for (int jj = 0; jj < 8; jj++) {
            m[jj]  = fmaxf(m[jj], __shfl_xor_sync(0xffffffffu, m[jj], off));
            sm[jj] += __shfl_xor_sync(0xffffffffu, sm[jj], off);
            sq[jj] += __shfl_xor_sync(0xffffffffu, sq[jj], off);
        }
    }
    if ((t & 7) == 0) {
        float* o = out + (size_t)bs * COUT + tc;
#pragma unroll
        for (int jj = 0; jj < 8; jj++) {
            o[jj] = m[jj];                       // raw max(h); normalized in pass 2
            atomicAdd(&g_sum[tc + jj], sm[jj]);
            atomicAdd(&g_sumsq[tc + jj], sq[jj]);
        }
    }
}

// ---------------- kernel: BN normalize + relu (in place on d_out) ----------------
__global__ __launch_bounds__(256) void norm_kernel(float* __restrict__ out,
                                                   const float* __restrict__ gamma,
                                                   const float* __restrict__ beta) {
    const int c = threadIdx.x;
    const size_t idx = (size_t)blockIdx.x * COUT + c;
    const float inv_m = 1.f / (float)M_TOT;
    float mean = g_sum[c] * inv_m;
    float var  = g_sumsq[c] * inv_m - mean * mean;
    float rstd = 1.f / sqrtf(var + BN_EPS);
    float h = out[idx];
    float v = (h - mean) * rstd * gamma[c] + beta[c];
    out[idx] = fmaxf(v, 0.f);
}

// ---------------- launch ----------------
extern "C" void kernel_launch(void* const* d_in, const int* in_sizes, int n_in,
                              void* d_out, int out_size) {
    const float* xyz    = (const float*)d_in[0];
    // d_in[1] = t  (unused by the reference)
    const float* points = (const float*)d_in[2];
    const float* W1     = (const float*)d_in[3];
    const float* b1     = (const float*)d_in[4];
    const float* Wc     = (const float*)d_in[5];
    const float* bc     = (const float*)d_in[6];
    const float* gamma  = (const float*)d_in[7];
    const float* beta   = (const float*)d_in[8];
    float* out = (float*)d_out;

    zero_stats_kernel<<<1, 256>>>();
    fps_kernel<<<B, 512>>>(xyz);
    feats_kernel<<<dim3(64, B), 256>>>(points, W1, b1);
    ballq_kernel<<<(B * S) / 16, 512>>>(xyz);
    group_gemm_kernel<<<B * S, 256>>>(Wc, bc, out);
    norm_kernel<<<(B * S * COUT) / 256, 256>>>(out, gamma, beta);
}

// round 6
// speedup vs baseline: 1.6359x; 1.6359x over previous
#include <cuda_runtime.h>
#include <cuda_bf16.h>
#include <cstdint>

// ---------------- problem constants ----------------
#define B       8
#define N       4096
#define S       1024          // NPOINT
#define NS      32            // NSAMPLE
#define CIN     64
#define CMLP    128
#define COUT    256
#define BN_EPS  1e-5f
#define M_TOT   (B*S*NS)      // 262144 samples per channel for BN

// ---------------- f32x2 helpers (GEMM only — NOT bit-exact-critical paths) ----
#define SPLAT2(d, v)       asm("mov.b64 %0, {%1,%1};" : "=l"(d) : "f"(v))
#define UNPACK2(lo, hi, d) asm("mov.b64 {%0,%1}, %2;" : "=f"(lo), "=f"(hi) : "l"(d))
#define FMA2(acc, a, b)    asm("fma.rn.f32x2 %0, %1, %2, %0;" : "+l"(acc) : "l"(a), "l"(b))

// ---------------- device scratch (no allocs allowed) ----------------
__device__ float4 g_cent[B * S];                     // FPS centroids (new_xyz)
__device__ int    g_gidx[B * S * NS];                // ball query indices (1 MB)
__device__ float  g_Wf[CIN * COUT];                  // fused W1@Wc   (64x256)
__device__ float  g_bf[COUT];                        // fused b1@Wc + bc
__device__ float  g_H[(size_t)B * N * COUT];         // points@Wf + bf  (33.5 MB)
__device__ float  g_sum[COUT];
__device__ float  g_sumsq[COUT];

// ---------------- kernel: zero BN stats ----------------
__global__ void zero_stats_kernel() {
    g_sum[threadIdx.x] = 0.f;
    g_sumsq[threadIdx.x] = 0.f;
}

// ---------------- kernel: farthest point sampling ----------------
// EXACT round-2 version (known bit-correct vs XLA). One block per batch,
// 512 threads, 8 points per thread. Scalar rn ops only — no packed math.
__global__ __launch_bounds__(512) void fps_kernel(const float* __restrict__ xyz) {
    const int b = blockIdx.x;
    const float* X = xyz + (size_t)b * N * 3;
    const int tid = threadIdx.x;
    const int lane = tid & 31, wid = tid >> 5;

    float px[8], py[8], pz[8], dmin[8];
#pragma unroll
    for (int j = 0; j < 8; j++) {
        int p = tid + j * 512;
        px[j] = X[p * 3 + 0];
        py[j] = X[p * 3 + 1];
        pz[j] = X[p * 3 + 2];
        dmin[j] = 1e10f;
    }

    __shared__ float s_wv[16];
    __shared__ int   s_wi[16];
    __shared__ int   s_far;
    __shared__ float s_c[3];
    if (tid == 0) s_far = 0;
    __syncthreads();

    for (int it = 0; it < S; it++) {
        if (tid == 0) {
            int f = s_far;
            float cx = X[f * 3 + 0], cy = X[f * 3 + 1], cz = X[f * 3 + 2];
            s_c[0] = cx; s_c[1] = cy; s_c[2] = cz;
            g_cent[b * S + it] = make_float4(cx, cy, cz, 0.f);
        }
        __syncthreads();
        const float cx = s_c[0], cy = s_c[1], cz = s_c[2];

        float bv = -1.f;  int bi = 0x7fffffff;
#pragma unroll
        for (int j = 0; j < 8; j++) {
            float dx = __fsub_rn(px[j], cx);
            float dy = __fsub_rn(py[j], cy);
            float dz = __fsub_rn(pz[j], cz);
            float d  = __fadd_rn(__fadd_rn(__fmul_rn(dx, dx), __fmul_rn(dy, dy)),
                                 __fmul_rn(dz, dz));
            float dm = fminf(dmin[j], d);
            dmin[j] = dm;
            if (dm > bv) { bv = dm; bi = tid + j * 512; }   // strict > keeps lowest index
        }
#pragma unroll
        for (int o = 16; o > 0; o >>= 1) {
            float ov = __shfl_down_sync(0xffffffffu, bv, o);
            int   oi = __shfl_down_sync(0xffffffffu, bi, o);
            if (ov > bv || (ov == bv && oi < bi)) { bv = ov; bi = oi; }
        }
        if (lane == 0) { s_wv[wid] = bv; s_wi[wid] = bi; }
        __syncthreads();
        if (wid == 0) {
            float v = (lane < 16) ? s_wv[lane] : -2.f;
            int   i = (lane < 16) ? s_wi[lane] : 0x7fffffff;
#pragma unroll
            for (int o = 16; o > 0; o >>= 1) {
                float ov = __shfl_down_sync(0xffffffffu, v, o);
                int   oi = __shfl_down_sync(0xffffffffu, i, o);
                if (ov > v || (ov == v && oi < i)) { v = ov; i = oi; }
            }
            if (lane == 0) s_far = i;
        }
    }
}

// ---------------- kernel: ball query ----------------
// 512 threads = 16 warps = 16 centroids per block; xyz tile staged in smem (SoA).
__global__ __launch_bounds__(512) void ballq_kernel(const float* __restrict__ xyz) {
    __shared__ float sx[N], sy[N], sz[N];     // 48 KB

    const float R2 = (float)(0.15 * 0.15);    // f64 product cast to f32, matching JAX
    const int tid  = threadIdx.x;
    const int w    = blockIdx.x * 16 + (tid >> 5);
    const int lane = tid & 31;
    const int b    = w >> 10;                 // 64 blocks per batch (16 | 1024)
    const float* X = xyz + (size_t)b * N * 3;

    for (int idx = tid; idx < N * 3; idx += 512) {
        float f = X[idx];
        int p = idx / 3, c = idx - p * 3;
        if (c == 0) sx[p] = f; else if (c == 1) sy[p] = f; else sz[p] = f;
    }
    __syncthreads();

    float4 cc = g_cent[w];
    int count = 0;
    int first = -1;
    int* out = g_gidx + w * NS;

    for (int c0 = 0; c0 < N; c0 += 32) {
        int p = c0 + lane;
        float dx = __fsub_rn(sx[p], cc.x);
        float dy = __fsub_rn(sy[p], cc.y);
        float dz = __fsub_rn(sz[p], cc.z);
        float d = __fadd_rn(__fadd_rn(__fmul_rn(dx, dx), __fmul_rn(dy, dy)),
                            __fmul_rn(dz, dz));
        bool ok = !(d > R2);
        unsigned m = __ballot_sync(0xffffffffu, ok);
        if (count == 0 && m) first = c0 + __ffs(m) - 1;
        int pos = count + __popc(m & ((1u << lane) - 1));
        if (ok && pos < NS) out[pos] = p;
        count += __popc(m);
        if (count >= NS) break;     // warp-uniform (count derived from ballot)
    }
    for (int i = count + lane; i < NS; i += 32) out[i] = first;
}

// ---------------- kernel: fuse weights  Wf = W1@Wc,  bf = b1@Wc + bc ----------
// grid 65: blocks 0..63 -> row i of W1; block 64 -> b1 row (+bc).
__global__ __launch_bounds__(256) void wfuse_kernel(const float* __restrict__ W1,
                                                    const float* __restrict__ b1,
                                                    const float* __restrict__ Wc,
                                                    const float* __restrict__ bc) {
    __shared__ float sv[CMLP];
    const int i = blockIdx.x;
    const int o = threadIdx.x;
    const float* src = (i < CIN) ? (W1 + i * CMLP) : b1;
    if (o < CMLP) sv[o] = src[o];
    __syncthreads();

    float acc = 0.f;
#pragma unroll 8
    for (int k = 0; k < CMLP; k++) acc += sv[k] * Wc[k * COUT + o];

    if (i < CIN) g_Wf[i * COUT + o] = acc;
    else         g_bf[o] = acc + bc[o];
}

// ---------------- kernel: H = points @ Wf + bf ----------------
// 512 blocks of 64 rows; 256 threads; per-thread 8 rows x 8 cols (f32x2 accs).
__global__ __launch_bounds__(256) void hgemm_kernel(const float* __restrict__ points) {
    __shared__ float Ps[64 * CIN];      // row-major A tile (16 KB); reads are
                                        // warp-uniform -> broadcast, no conflicts
    __shared__ float Wf[CIN * COUT];    // full fused weight (64 KB)

    const int r0 = blockIdx.x * 64;     // global row over B*N
    const int t  = threadIdx.x;
    const int ty = t >> 5;              // warp id -> row group ty*8 (warp-uniform)
    const int tx = t & 31;              // lane -> col group tx*8

    for (int i = t; i < 64 * CIN; i += 256)
        Ps[i] = points[(size_t)r0 * CIN + i];
    {
        const float4* src = (const float4*)g_Wf;
        float4* dst = (float4*)Wf;
#pragma unroll
        for (int i = 0; i < 16; i++) dst[t + i * 256] = src[t + i * 256];
    }
    __syncthreads();

    unsigned long long acc[8][4];       // [row][colpair]
#pragma unroll
    for (int i = 0; i < 8; i++)
#pragma unroll
        for (int j = 0; j < 4; j++) acc[i][j] = 0ull;

#pragma unroll 4
    for (int k = 0; k < CIN; k++) {
        ulonglong2 wq0 = *(const ulonglong2*)(Wf + k * COUT + tx * 8);
        ulonglong2 wq1 = *(const ulonglong2*)(Wf + k * COUT + tx * 8 + 4);
        unsigned long long wp0 = wq0.x, wp1 = wq0.y, wp2 = wq1.x, wp3 = wq1.y;
#pragma unroll
        for (int ri = 0; ri < 8; ri++) {
            float av = Ps[(ty * 8 + ri) * CIN + k];     // broadcast
            unsigned long long a2; SPLAT2(a2, av);
            FMA2(acc[ri][0], a2, wp0); FMA2(acc[ri][1], a2, wp1);
            FMA2(acc[ri][2], a2, wp2); FMA2(acc[ri][3], a2, wp3);
        }
    }

    float bias[8];
    *(float4*)(bias)     = *(const float4*)(g_bf + tx * 8);
    *(float4*)(bias + 4) = *(const float4*)(g_bf + tx * 8 + 4);

#pragma unroll
    for (int ri = 0; ri < 8; ri++) {
        float v[8];
#pragma unroll
        for (int j = 0; j < 4; j++) {
            float lo, hi; UNPACK2(lo, hi, acc[ri][j]);
            v[2 * j] = lo + bias[2 * j]; v[2 * j + 1] = hi + bias[2 * j + 1];
        }
        float* o = g_H + ((size_t)r0 + ty * 8 + ri) * COUT + tx * 8;
        *(float4*)(o)     = *(float4*)(v);
        *(float4*)(o + 4) = *(float4*)(v + 4);
    }
}

// ---------------- kernel: gather-max pool + BN stats ----------------
// one block per (b,s): out[bs,c] = max_n H[b, gidx[bs,n], c]; also sum/sumsq.
__global__ __launch_bounds__(256) void pool_kernel(float* __restrict__ out) {
    __shared__ int rows[NS];
    const int bs = blockIdx.x;
    const int t  = threadIdx.x;
    if (t < NS) rows[t] = g_gidx[bs * NS + t];
    __syncthreads();

    const float* Hb = g_H + ((size_t)(bs >> 10) * N) * COUT + t;   // channel t
    float maxv = -1e30f, sum = 0.f, sq = 0.f;
#pragma unroll 8
    for (int n = 0; n < NS; n++) {
        float v = Hb[(size_t)rows[n] * COUT];
        maxv = fmaxf(maxv, v);
        sum += v;
        sq  += v * v;
    }
    out[(size_t)bs * COUT + t] = maxv;          // raw max(h); normalized in pass 2
    atomicAdd(&g_sum[t], sum);
    atomicAdd(&g_sumsq[t], sq);
}

// ---------------- kernel: BN normalize + relu (in place on d_out) ----------------
__global__ __launch_bounds__(256) void norm_kernel(float* __restrict__ out,
                                                   const float* __restrict__ gamma,
                                                   const float* __restrict__ beta) {
    const int c = threadIdx.x;
    const size_t idx = (size_t)blockIdx.x * COUT + c;
    const float inv_m = 1.f / (float)M_TOT;
    float mean = g_sum[c] * inv_m;
    float var  = g_sumsq[c] * inv_m - mean * mean;
    float rstd = 1.f / sqrtf(var + BN_EPS);
    float h = out[idx];
    float v = (h - mean) * rstd * gamma[c] + beta[c];
    out[idx] = fmaxf(v, 0.f);
}

// ---------------- launch ----------------
extern "C" void kernel_launch(void* const* d_in, const int* in_sizes, int n_in,
                              void* d_out, int out_size) {
    const float* xyz    = (const float*)d_in[0];
    // d_in[1] = t  (unused by the reference)
    const float* points = (const float*)d_in[2];
    const float* W1     = (const float*)d_in[3];
    const float* b1     = (const float*)d_in[4];
    const float* Wc     = (const float*)d_in[5];
    const float* bc     = (const float*)d_in[6];
    const float* gamma  = (const float*)d_in[7];
    const float* beta   = (const float*)d_in[8];
    float* out = (float*)d_out;

    zero_stats_kernel<<<1, 256>>>();
    fps_kernel<<<B, 512>>>(xyz);
    ballq_kernel<<<(B * S) / 16, 512>>>(xyz);
    wfuse_kernel<<<CIN + 1, 256>>>(W1, b1, Wc, bc);
    hgemm_kernel<<<(B * N) / 64, 256>>>(points);
    pool_kernel<<<B * S, 256>>>(out);
    norm_kernel<<<(B * S * COUT) / 256, 256>>>(out, gamma, beta);
}

// round 7
// speedup vs baseline: 2.0439x; 1.2494x over previous
#include <cuda_runtime.h>
#include <cuda_bf16.h>
#include <cstdint>

// ---------------- problem constants ----------------
#define B       8
#define N       4096
#define S       1024          // NPOINT
#define NS      32            // NSAMPLE
#define CIN     64
#define CMLP    128
#define COUT    256
#define BN_EPS  1e-5f
#define M_TOT   (B*S*NS)      // 262144 samples per channel for BN

// ---------------- f32x2 helpers (GEMM only — NOT bit-exact-critical paths) ----
#define SPLAT2(d, v)       asm("mov.b64 %0, {%1,%1};" : "=l"(d) : "f"(v))
#define UNPACK2(lo, hi, d) asm("mov.b64 {%0,%1}, %2;" : "=f"(lo), "=f"(hi) : "l"(d))
#define FMA2(acc, a, b)    asm("fma.rn.f32x2 %0, %1, %2, %0;" : "+l"(acc) : "l"(a), "l"(b))

// ---------------- device scratch (no allocs allowed) ----------------
__device__ float4 g_cent[B * S];                     // FPS centroids (new_xyz)
__device__ int    g_gidx[B * S * NS];                // ball query indices (1 MB)
__device__ float  g_Wf[CIN * COUT];                  // fused W1@Wc   (64x256)
__device__ float  g_bf[COUT];                        // fused b1@Wc + bc
__device__ float  g_H[(size_t)B * N * COUT];         // points@Wf + bf  (33.5 MB)
__device__ float  g_sum[COUT];
__device__ float  g_sumsq[COUT];

// ---------------- kernel: zero BN stats ----------------
__global__ void zero_stats_kernel() {
    g_sum[threadIdx.x] = 0.f;
    g_sumsq[threadIdx.x] = 0.f;
}

// ---------------- kernel: farthest point sampling ----------------
// One block per batch, 512 threads, 8 points/thread. Distance + min + argmax
// value sequence is byte-identical to the round-5 passing version (bit-exact
// vs XLA). Only the reduction PLUMBING changed:
//  - warp level: REDUX max on float bits (dmin>=0 so bits are monotonic),
//    then REDUX min on indices among threads holding the max -> identical
//    (max value, lowest index) semantics.
//  - block level: per-warp u64 key (val_bits<<32 | (MAXI-idx)) in smem;
//    after ONE barrier every thread scans the 16 keys and resolves the winner
//    locally (u64 max == max value, lowest index). Double-buffered keys make
//    one barrier per iteration sufficient.
//  - every thread then loads the centroid directly from X (uniform address ->
//    L1 broadcast), removing the tid0->smem->barrier round trip.
__global__ __launch_bounds__(512) void fps_kernel(const float* __restrict__ xyz) {
    const int b = blockIdx.x;
    const float* X = xyz + (size_t)b * N * 3;
    const int tid = threadIdx.x;
    const int lane = tid & 31, wid = tid >> 5;

    float px[8], py[8], pz[8], dmin[8];
#pragma unroll
    for (int j = 0; j < 8; j++) {
        int p = tid + j * 512;
        px[j] = X[p * 3 + 0];
        py[j] = X[p * 3 + 1];
        pz[j] = X[p * 3 + 2];
        dmin[j] = 1e10f;
    }

    __shared__ unsigned long long s_key[2][16];

    int f = 0;                                   // farthest index (block-uniform)
    for (int it = 0; it < S; it++) {
        // uniform-address loads -> one L1 broadcast per component
        const float cx = X[f * 3 + 0], cy = X[f * 3 + 1], cz = X[f * 3 + 2];
        if (tid == 0) g_cent[b * S + it] = make_float4(cx, cy, cz, 0.f);

        float bv = -1.f;  int bi = 0x7fffffff;
#pragma unroll
        for (int j = 0; j < 8; j++) {
            float dx = __fsub_rn(px[j], cx);
            float dy = __fsub_rn(py[j], cy);
            float dz = __fsub_rn(pz[j], cz);
            float d  = __fadd_rn(__fadd_rn(__fmul_rn(dx, dx), __fmul_rn(dy, dy)),
                                 __fmul_rn(dz, dz));
            float dm = fminf(dmin[j], d);
            dmin[j] = dm;
            if (dm > bv) { bv = dm; bi = tid + j * 512; }   // strict > keeps lowest index
        }

        // warp reduce: max value (bits), then min index among holders of the max
        unsigned wv = __reduce_max_sync(0xffffffffu, __float_as_uint(bv));
        unsigned cand = (__float_as_uint(bv) == wv) ? (unsigned)bi : 0x7fffffffu;
        unsigned wbi = __reduce_min_sync(0xffffffffu, cand);

        if (lane == 0)
            s_key[it & 1][wid] =
                ((unsigned long long)wv << 32) | (unsigned long long)(0x7fffffffu - wbi);
        __syncthreads();

        // block reduce: every thread scans the 16 keys (broadcast reads)
        const unsigned long long* sk = s_key[it & 1];
        unsigned long long best = sk[0];
#pragma unroll
        for (int i = 1; i < 16; i++) {
            unsigned long long k2 = sk[i];
            if (k2 > best) best = k2;
        }
        f = (int)(0x7fffffffu - (unsigned)(best & 0xffffffffu));
    }
}

// ---------------- kernel: ball query ----------------
// 512 threads = 16 warps = 16 centroids per block; xyz tile staged in smem (SoA).
__global__ __launch_bounds__(512) void ballq_kernel(const float* __restrict__ xyz) {
    __shared__ float sx[N], sy[N], sz[N];     // 48 KB

    const float R2 = (float)(0.15 * 0.15);    // f64 product cast to f32, matching JAX
    const int tid  = threadIdx.x;
    const int w    = blockIdx.x * 16 + (tid >> 5);
    const int lane = tid & 31;
    const int b    = w >> 10;                 // 64 blocks per batch (16 | 1024)
    const float* X = xyz + (size_t)b * N * 3;

    for (int idx = tid; idx < N * 3; idx += 512) {
        float f = X[idx];
        int p = idx / 3, c = idx - p * 3;
        if (c == 0) sx[p] = f; else if (c == 1) sy[p] = f; else sz[p] = f;
    }
    __syncthreads();

    float4 cc = g_cent[w];
    int count = 0;
    int first = -1;
    int* out = g_gidx + w * NS;

    for (int c0 = 0; c0 < N; c0 += 32) {
        int p = c0 + lane;
        float dx = __fsub_rn(sx[p], cc.x);
        float dy = __fsub_rn(sy[p], cc.y);
        float dz = __fsub_rn(sz[p], cc.z);
        float d = __fadd_rn(__fadd_rn(__fmul_rn(dx, dx), __fmul_rn(dy, dy)),
                            __fmul_rn(dz, dz));
        bool ok = !(d > R2);
        unsigned m = __ballot_sync(0xffffffffu, ok);
        if (count == 0 && m) first = c0 + __ffs(m) - 1;
        int pos = count + __popc(m & ((1u << lane) - 1));
        if (ok && pos < NS) out[pos] = p;
        count += __popc(m);
        if (count >= NS) break;     // warp-uniform (count derived from ballot)
    }
    for (int i = count + lane; i < NS; i += 32) out[i] = first;
}

// ---------------- kernel: fuse weights  Wf = W1@Wc,  bf = b1@Wc + bc ----------
// grid 65: blocks 0..63 -> row i of W1; block 64 -> b1 row (+bc).
__global__ __launch_bounds__(256) void wfuse_kernel(const float* __restrict__ W1,
                                                    const float* __restrict__ b1,
                                                    const float* __restrict__ Wc,
                                                    const float* __restrict__ bc) {
    __shared__ float sv[CMLP];
    const int i = blockIdx.x;
    const int o = threadIdx.x;
    const float* src = (i < CIN) ? (W1 + i * CMLP) : b1;
    if (o < CMLP) sv[o] = src[o];
    __syncthreads();

    float acc = 0.f;
#pragma unroll 8
    for (int k = 0; k < CMLP; k++) acc += sv[k] * Wc[k * COUT + o];

    if (i < CIN) g_Wf[i * COUT + o] = acc;
    else         g_bf[o] = acc + bc[o];
}

// ---------------- kernel: H = points @ Wf + bf ----------------
// 512 blocks of 64 rows; 256 threads; per-thread 8 rows x 8 cols (f32x2 accs).
__global__ __launch_bounds__(256) void hgemm_kernel(const float* __restrict__ points) {
    __shared__ float Ps[64 * CIN];      // row-major A tile (16 KB)
    __shared__ float Wf[CIN * COUT];    // full fused weight (64 KB)

    const int r0 = blockIdx.x * 64;     // global row over B*N
    const int t  = threadIdx.x;
    const int ty = t >> 5;              // warp id -> row group ty*8 (warp-uniform)
    const int tx = t & 31;              // lane -> col group tx*8

    for (int i = t; i < 64 * CIN; i += 256)
        Ps[i] = points[(size_t)r0 * CIN + i];
    {
        const float4* src = (const float4*)g_Wf;
        float4* dst = (float4*)Wf;
#pragma unroll
        for (int i = 0; i < 16; i++) dst[t + i * 256] = src[t + i * 256];
    }
    __syncthreads();

    unsigned long long acc[8][4];       // [row][colpair]
#pragma unroll
    for (int i = 0; i < 8; i++)
#pragma unroll
        for (int j = 0; j < 4; j++) acc[i][j] = 0ull;

#pragma unroll 4
    for (int k = 0; k < CIN; k++) {
        ulonglong2 wq0 = *(const ulonglong2*)(Wf + k * COUT + tx * 8);
        ulonglong2 wq1 = *(const ulonglong2*)(Wf + k * COUT + tx * 8 + 4);
        unsigned long long wp0 = wq0.x, wp1 = wq0.y, wp2 = wq1.x, wp3 = wq1.y;
#pragma unroll
        for (int ri = 0; ri < 8; ri++) {
            float av = Ps[(ty * 8 + ri) * CIN + k];     // broadcast
            unsigned long long a2; SPLAT2(a2, av);
            FMA2(acc[ri][0], a2, wp0); FMA2(acc[ri][1], a2, wp1);
            FMA2(acc[ri][2], a2, wp2); FMA2(acc[ri][3], a2, wp3);
        }
    }

    float bias[8];
    *(float4*)(bias)     = *(const float4*)(g_bf + tx * 8);
    *(float4*)(bias + 4) = *(const float4*)(g_bf + tx * 8 + 4);

#pragma unroll
    for (int ri = 0; ri < 8; ri++) {
        float v[8];
#pragma unroll
        for (int j = 0; j < 4; j++) {
            float lo, hi; UNPACK2(lo, hi, acc[ri][j]);
            v[2 * j] = lo + bias[2 * j]; v[2 * j + 1] = hi + bias[2 * j + 1];
        }
        float* o = g_H + ((size_t)r0 + ty * 8 + ri) * COUT + tx * 8;
        *(float4*)(o)     = *(float4*)(v);
        *(float4*)(o + 4) = *(float4*)(v + 4);
    }
}

// ---------------- kernel: gather-max pool + BN stats ----------------
// one block per (b,s): out[bs,c] = max_n H[b, gidx[bs,n], c]; also sum/sumsq.
__global__ __launch_bounds__(256) void pool_kernel(float* __restrict__ out) {
    __shared__ int rows[NS];
    const int bs = blockIdx.x;
    const int t  = threadIdx.x;
    if (t < NS) rows[t] = g_gidx[bs * NS + t];
    __syncthreads();

    const float* Hb = g_H + ((size_t)(bs >> 10) * N) * COUT + t;   // channel t
    float maxv = -1e30f, sum = 0.f, sq = 0.f;
#pragma unroll 8
    for (int n = 0; n < NS; n++) {
        float v = Hb[(size_t)rows[n] * COUT];
        maxv = fmaxf(maxv, v);
        sum += v;
        sq  += v * v;
    }
    out[(size_t)bs * COUT + t] = maxv;          // raw max(h); normalized in pass 2
    atomicAdd(&g_sum[t], sum);
    atomicAdd(&g_sumsq[t], sq);
}

// ---------------- kernel: BN normalize + relu (in place on d_out) ----------------
__global__ __launch_bounds__(256) void norm_kernel(float* __restrict__ out,
                                                   const float* __restrict__ gamma,
                                                   const float* __restrict__ beta) {
    const int c = threadIdx.x;
    const size_t idx = (size_t)blockIdx.x * COUT + c;
    const float inv_m = 1.f / (float)M_TOT;
    float mean = g_sum[c] * inv_m;
    float var  = g_sumsq[c] * inv_m - mean * mean;
    float rstd = 1.f / sqrtf(var + BN_EPS);
    float h = out[idx];
    float v = (h - mean) * rstd * gamma[c] + beta[c];
    out[idx] = fmaxf(v, 0.f);
}

// ---------------- launch ----------------
extern "C" void kernel_launch(void* const* d_in, const int* in_sizes, int n_in,
                              void* d_out, int out_size) {
    const float* xyz    = (const float*)d_in[0];
    // d_in[1] = t  (unused by the reference)
    const float* points = (const float*)d_in[2];
    const float* W1     = (const float*)d_in[3];
    const float* b1     = (const float*)d_in[4];
    const float* Wc     = (const float*)d_in[5];
    const float* bc     = (const float*)d_in[6];
    const float* gamma  = (const float*)d_in[7];
    const float* beta   = (const float*)d_in[8];
    float* out = (float*)d_out;

    zero_stats_kernel<<<1, 256>>>();
    fps_kernel<<<B, 512>>>(xyz);
    ballq_kernel<<<(B * S) / 16, 512>>>(xyz);
    wfuse_kernel<<<CIN + 1, 256>>>(W1, b1, Wc, bc);
    hgemm_kernel<<<(B * N) / 64, 256>>>(points);
    pool_kernel<<<B * S, 256>>>(out);
    norm_kernel<<<(B * S * COUT) / 256, 256>>>(out, gamma, beta);
}

// round 9
// speedup vs baseline: 2.1864x; 1.0697x over previous
#include <cuda_runtime.h>
#include <cuda_bf16.h>
#include <cstdint>

// ---------------- problem constants ----------------
#define B       8
#define N       4096
#define S       1024          // NPOINT
#define NS      32            // NSAMPLE
#define CIN     64
#define CMLP    128
#define COUT    256
#define BN_EPS  1e-5f
#define M_TOT   (B*S*NS)      // 262144 samples per channel for BN

// ---------------- f32x2 helpers ----------------
#define PACK2(d, lo, hi)   asm("mov.b64 %0, {%1,%2};" : "=l"(d) : "f"(lo), "f"(hi))
#define SPLAT2(d, v)       asm("mov.b64 %0, {%1,%1};" : "=l"(d) : "f"(v))
#define UNPACK2(lo, hi, d) asm("mov.b64 {%0,%1}, %2;" : "=f"(lo), "=f"(hi) : "l"(d))
#define ADD2(o, a, b)      asm("add.rn.f32x2 %0, %1, %2;" : "=l"(o) : "l"(a), "l"(b))
#define MUL2(o, a, b)      asm("mul.rn.f32x2 %0, %1, %2;" : "=l"(o) : "l"(a), "l"(b))
#define FMA2(acc, a, b)    asm("fma.rn.f32x2 %0, %1, %2, %0;" : "+l"(acc) : "l"(a), "l"(b))

// ---------------- device scratch (no allocs allowed) ----------------
__device__ float4 g_cent[B * S];                     // FPS centroids (new_xyz)
__device__ int    g_gidx[B * S * NS];                // ball query indices (1 MB)
__device__ float  g_Wf[CIN * COUT];                  // fused W1@Wc   (64x256)
__device__ float  g_bf[COUT];                        // fused b1@Wc + bc
__device__ float  g_H[(size_t)B * N * COUT];         // points@Wf + bf  (33.5 MB)
__device__ float  g_sum[COUT];
__device__ float  g_sumsq[COUT];

// ---------------- kernel: zero BN stats ----------------
__global__ void zero_stats_kernel() {
    g_sum[threadIdx.x] = 0.f;
    g_sumsq[threadIdx.x] = 0.f;
}

// ---------------- kernel: farthest point sampling ----------------
// Round-7 structure (REDUX + single-barrier key scan), with ONE change:
// distance arithmetic packed as f32x2. Exactness argument:
//  - add/mul.rn.f32x2 are per-lane .rn ops (no .ftz used) -> each half is
//    bitwise identical to the scalar __fadd_rn/__fmul_rn sequence.
//  - subtract realized as a + (-c); negation is exact in IEEE-754.
//  - min/argmax compares remain scalar, in the same ascending-p order,
//    so the (value, lowest-index) winner stream is unchanged.
__global__ __launch_bounds__(512) void fps_kernel(const float* __restrict__ xyz) {
    const int b = blockIdx.x;
    const float* X = xyz + (size_t)b * N * 3;
    const int tid = threadIdx.x;
    const int lane = tid & 31, wid = tid >> 5;

    unsigned long long px2[4], py2[4], pz2[4];
    float dm[8];
#pragma unroll
    for (int jj = 0; jj < 4; jj++) {
        int p0 = tid + (2 * jj) * 512;
        int p1 = p0 + 512;
        PACK2(px2[jj], X[p0 * 3 + 0], X[p1 * 3 + 0]);
        PACK2(py2[jj], X[p0 * 3 + 1], X[p1 * 3 + 1]);
        PACK2(pz2[jj], X[p0 * 3 + 2], X[p1 * 3 + 2]);
        dm[2 * jj] = 1e10f; dm[2 * jj + 1] = 1e10f;
    }

    __shared__ unsigned long long s_key[2][16];

    int f = 0;                                   // farthest index (block-uniform)
    for (int it = 0; it < S; it++) {
        // uniform-address loads -> one L1 broadcast per component
        const float cx = X[f * 3 + 0], cy = X[f * 3 + 1], cz = X[f * 3 + 2];
        if (tid == 0) g_cent[b * S + it] = make_float4(cx, cy, cz, 0.f);

        unsigned long long ncx2, ncy2, ncz2;
        {
            float nx = -cx, ny = -cy, nz = -cz;
            SPLAT2(ncx2, nx); SPLAT2(ncy2, ny); SPLAT2(ncz2, nz);
        }

        float bv = -1.f;  int bi = 0x7fffffff;
#pragma unroll
        for (int jj = 0; jj < 4; jj++) {
            unsigned long long dx, dy, dz, q0, q1, q2, d2;
            ADD2(dx, px2[jj], ncx2); MUL2(q0, dx, dx);
            ADD2(dy, py2[jj], ncy2); MUL2(q1, dy, dy);
            ADD2(dz, pz2[jj], ncz2); MUL2(q2, dz, dz);
            ADD2(q0, q0, q1);        // (dx*dx + dy*dy)
            ADD2(d2, q0, q2);        // ... + dz*dz
            float d0, d1; UNPACK2(d0, d1, d2);
            float m0 = fminf(dm[2 * jj], d0);     dm[2 * jj] = m0;
            if (m0 > bv) { bv = m0; bi = tid + (2 * jj) * 512; }
            float m1 = fminf(dm[2 * jj + 1], d1); dm[2 * jj + 1] = m1;
            if (m1 > bv) { bv = m1; bi = tid + (2 * jj + 1) * 512; }
        }

        // warp reduce: max value (bits), then min index among holders of the max
        unsigned wv = __reduce_max_sync(0xffffffffu, __float_as_uint(bv));
        unsigned cand = (__float_as_uint(bv) == wv) ? (unsigned)bi : 0x7fffffffu;
        unsigned wbi = __reduce_min_sync(0xffffffffu, cand);

        if (lane == 0)
            s_key[it & 1][wid] =
                ((unsigned long long)wv << 32) | (unsigned long long)(0x7fffffffu - wbi);
        __syncthreads();

        // block reduce: every thread scans the 16 keys (broadcast reads)
        const unsigned long long* sk = s_key[it & 1];
        unsigned long long best = sk[0];
#pragma unroll
        for (int i = 1; i < 16; i++) {
            unsigned long long k2 = sk[i];
            if (k2 > best) best = k2;
        }
        f = (int)(0x7fffffffu - (unsigned)(best & 0xffffffffu));
    }
}

// ---------------- kernel: ball query ----------------
// 512 threads = 16 warps = 16 centroids per block; xyz tile staged in smem (SoA).
__global__ __launch_bounds__(512) void ballq_kernel(const float* __restrict__ xyz) {
    __shared__ float sx[N], sy[N], sz[N];     // 48 KB

    const float R2 = (float)(0.15 * 0.15);    // f64 product cast to f32, matching JAX
    const int tid  = threadIdx.x;
    const int w    = blockIdx.x * 16 + (tid >> 5);
    const int lane = tid & 31;
    const int b    = w >> 10;                 // 64 blocks per batch (16 | 1024)
    const float* X = xyz + (size_t)b * N * 3;

    for (int idx = tid; idx < N * 3; idx += 512) {
        float f = X[idx];
        int p = idx / 3, c = idx - p * 3;
        if (c == 0) sx[p] = f; else if (c == 1) sy[p] = f; else sz[p] = f;
    }
    __syncthreads();

    float4 cc = g_cent[w];
    int count = 0;
    int first = -1;
    int* out = g_gidx + w * NS;

    for (int c0 = 0; c0 < N; c0 += 32) {
        int p = c0 + lane;
        float dx = __fsub_rn(sx[p], cc.x);
        float dy = __fsub_rn(sy[p], cc.y);
        float dz = __fsub_rn(sz[p], cc.z);
        float d = __fadd_rn(__fadd_rn(__fmul_rn(dx, dx), __fmul_rn(dy, dy)),
                            __fmul_rn(dz, dz));
        bool ok = !(d > R2);
        unsigned m = __ballot_sync(0xffffffffu, ok);
        if (count == 0 && m) first = c0 + __ffs(m) - 1;
        int pos = count + __popc(m & ((1u << lane) - 1));
        if (ok && pos < NS) out[pos] = p;
        count += __popc(m);
        if (count >= NS) break;     // warp-uniform (count derived from ballot)
    }
    for (int i = count + lane; i < NS; i += 32) out[i] = first;
}

// ---------------- kernel: fuse weights  Wf = W1@Wc,  bf = b1@Wc + bc ----------
__global__ __launch_bounds__(256) void wfuse_kernel(const float* __restrict__ W1,
                                                    const float* __restrict__ b1,
                                                    const float* __restrict__ Wc,
                                                    const float* __restrict__ bc) {
    __shared__ float sv[CMLP];
    const int i = blockIdx.x;
    const int o = threadIdx.x;
    const float* src = (i < CIN) ? (W1 + i * CMLP) : b1;
    if (o < CMLP) sv[o] = src[o];
    __syncthreads();

    float acc = 0.f;
#pragma unroll 8
    for (int k = 0; k < CMLP; k++) acc += sv[k] * Wc[k * COUT + o];

    if (i < CIN) g_Wf[i * COUT + o] = acc;
    else         g_bf[o] = acc + bc[o];
}

// ---------------- kernel: H = points @ Wf + bf ----------------
// 512 blocks of 64 rows; 256 threads; per-thread 8 rows x 8 cols (f32x2 accs).
__global__ __launch_bounds__(256) void hgemm_kernel(const float* __restrict__ points) {
    __shared__ float Ps[64 * CIN];      // row-major A tile (16 KB)
    __shared__ float Wf[CIN * COUT];    // full fused weight (64 KB)

    const int r0 = blockIdx.x * 64;     // global row over B*N
    const int t  = threadIdx.x;
    const int ty = t >> 5;              // warp id -> row group ty*8 (warp-uniform)
    const int tx = t & 31;              // lane -> col group tx*8

    for (int i = t; i < 64 * CIN; i += 256)
        Ps[i] = points[(size_t)r0 * CIN + i];
    {
        const float4* src = (const float4*)g_Wf;
        float4* dst = (float4*)Wf;
#pragma unroll
        for (int i = 0; i < 16; i++) dst[t + i * 256] = src[t + i * 256];
    }
    __syncthreads();

    unsigned long long acc[8][4];       // [row][colpair]
#pragma unroll
    for (int i = 0; i < 8; i++)
#pragma unroll
        for (int j = 0; j < 4; j++) acc[i][j] = 0ull;

#pragma unroll 4
    for (int k = 0; k < CIN; k++) {
        ulonglong2 wq0 = *(const ulonglong2*)(Wf + k * COUT + tx * 8);
        ulonglong2 wq1 = *(const ulonglong2*)(Wf + k * COUT + tx * 8 + 4);
        unsigned long long wp0 = wq0.x, wp1 = wq0.y, wp2 = wq1.x, wp3 = wq1.y;
#pragma unroll
        for (int ri = 0; ri < 8; ri++) {
            float av = Ps[(ty * 8 + ri) * CIN + k];     // broadcast
            unsigned long long a2; SPLAT2(a2, av);
            FMA2(acc[ri][0], a2, wp0); FMA2(acc[ri][1], a2, wp1);
            FMA2(acc[ri][2], a2, wp2); FMA2(acc[ri][3], a2, wp3);
        }
    }

    float bias[8];
    *(float4*)(bias)     = *(const float4*)(g_bf + tx * 8);
    *(float4*)(bias + 4) = *(const float4*)(g_bf + tx * 8 + 4);

#pragma unroll
    for (int ri = 0; ri < 8; ri++) {
        float v[8];
#pragma unroll
        for (int j = 0; j < 4; j++) {
            float lo, hi; UNPACK2(lo, hi, acc[ri][j]);
            v[2 * j] = lo + bias[2 * j]; v[2 * j + 1] = hi + bias[2 * j + 1];
        }
        float* o = g_H + ((size_t)r0 + ty * 8 + ri) * COUT + tx * 8;
        *(float4*)(o)     = *(float4*)(v);
        *(float4*)(o + 4) = *(float4*)(v + 4);
    }
}

// ---------------- kernel: gather-max pool + BN stats ----------------
__global__ __launch_bounds__(256) void pool_kernel(float* __restrict__ out) {
    __shared__ int rows[NS];
    const int bs = blockIdx.x;
    const int t  = threadIdx.x;
    if (t < NS) rows[t] = g_gidx[bs * NS + t];
    __syncthreads();

    const float* Hb = g_H + ((size_t)(bs >> 10) * N) * COUT + t;   // channel t
    float maxv = -1e30f, sum = 0.f, sq = 0.f;
#pragma unroll 8
    for (int n = 0; n < NS; n++) {
        float v = Hb[(size_t)rows[n] * COUT];
        maxv = fmaxf(maxv, v);
        sum += v;
        sq  += v * v;
    }
    out[(size_t)bs * COUT + t] = maxv;          // raw max(h); normalized in pass 2
    atomicAdd(&g_sum[t], sum);
    atomicAdd(&g_sumsq[t], sq);
}

// ---------------- kernel: BN normalize + relu (in place on d_out) ----------------
__global__ __launch_bounds__(256) void norm_kernel(float* __restrict__ out,
                                                   const float* __restrict__ gamma,
                                                   const float* __restrict__ beta) {
    const int c = threadIdx.x;
    const size_t idx = (size_t)blockIdx.x * COUT + c;
    const float inv_m = 1.f / (float)M_TOT;
    float mean = g_sum[c] * inv_m;
    float var  = g_sumsq[c] * inv_m - mean * mean;
    float rstd = 1.f / sqrtf(var + BN_EPS);
    float h = out[idx];
    float v = (h - mean) * rstd * gamma[c] + beta[c];
    out[idx] = fmaxf(v, 0.f);
}

// ---------------- launch ----------------
extern "C" void kernel_launch(void* const* d_in, const int* in_sizes, int n_in,
                              void* d_out, int out_size) {
    const float* xyz    = (const float*)d_in[0];
    // d_in[1] = t  (unused by the reference)
    const float* points = (const float*)d_in[2];
    const float* W1     = (const float*)d_in[3];
    const float* b1     = (const float*)d_in[4];
    const float* Wc     = (const float*)d_in[5];
    const float* bc     = (const float*)d_in[6];
    const float* gamma  = (const float*)d_in[7];
    const float* beta   = (const float*)d_in[8];
    float* out = (float*)d_out;

    zero_stats_kernel<<<1, 256>>>();
    fps_kernel<<<B, 512>>>(xyz);
    ballq_kernel<<<(B * S) / 16, 512>>>(xyz);
    wfuse_kernel<<<CIN + 1, 256>>>(W1, b1, Wc, bc);
    hgemm_kernel<<<(B * N) / 64, 256>>>(points);
    pool_kernel<<<B * S, 256>>>(out);
    norm_kernel<<<(B * S * COUT) / 256, 256>>>(out, gamma, beta);
}

// round 10
// speedup vs baseline: 2.6785x; 1.2251x over previous
#include <cuda_runtime.h>
#include <cuda_bf16.h>
#include <cstdint>

// ---------------- problem constants ----------------
#define B       8
#define N       4096
#define S       1024          // NPOINT
#define NS      32            // NSAMPLE
#define CIN     64
#define CMLP    128
#define COUT    256
#define BN_EPS  1e-5f
#define M_TOT   (B*S*NS)      // 262144 samples per channel for BN

// ---------------- f32x2 helpers ----------------
#define PACK2(d, lo, hi)   asm("mov.b64 %0, {%1,%2};" : "=l"(d) : "f"(lo), "f"(hi))
#define SPLAT2(d, v)       asm("mov.b64 %0, {%1,%1};" : "=l"(d) : "f"(v))
#define UNPACK2(lo, hi, d) asm("mov.b64 {%0,%1}, %2;" : "=f"(lo), "=f"(hi) : "l"(d))
#define ADD2(o, a, b)      asm("add.rn.f32x2 %0, %1, %2;" : "=l"(o) : "l"(a), "l"(b))
#define MUL2(o, a, b)      asm("mul.rn.f32x2 %0, %1, %2;" : "=l"(o) : "l"(a), "l"(b))
#define FMA2(acc, a, b)    asm("fma.rn.f32x2 %0, %1, %2, %0;" : "+l"(acc) : "l"(a), "l"(b))

// ---------------- device scratch (no allocs allowed) ----------------
__device__ float4 g_cent[B * S];                     // FPS centroids (new_xyz)
__device__ int    g_gidx[B * S * NS];                // ball query indices (1 MB)
__device__ float  g_Wf[CIN * COUT];                  // fused W1@Wc   (64x256)
__device__ float  g_bf[COUT];                        // fused b1@Wc + bc
__device__ float  g_H[(size_t)B * N * COUT];         // points@Wf + bf  (33.5 MB)
__device__ float  g_sum[COUT];
__device__ float  g_sumsq[COUT];

// ---------------- kernel: zero BN stats ----------------
__global__ void zero_stats_kernel() {
    g_sum[threadIdx.x] = 0.f;
    g_sumsq[threadIdx.x] = 0.f;
}

// ---------------- kernel: farthest point sampling ----------------
// 256 threads (8 warps), 16 points/thread as 8 f32x2 pairs. Same REDUX +
// single-barrier u64-key scheme as the passing round-9 kernel, but with only
// 8 keys to scan (half the redundant block-reduce issue work) and fewer
// warps per SMSP contending on the barrier.
// Result is mapping-independent: per-thread scan ascends in global p with
// strict >, warp REDUX takes the min global index among max-holders, and the
// key encoding (val<<32)|(0x7fffffff-idx) makes u64-max == (max val, min idx).
__global__ __launch_bounds__(256) void fps_kernel(const float* __restrict__ xyz) {
    const int b = blockIdx.x;
    const float* X = xyz + (size_t)b * N * 3;
    const int tid = threadIdx.x;
    const int lane = tid & 31, wid = tid >> 5;

    unsigned long long px2[8], py2[8], pz2[8];
    float dm[16];
#pragma unroll
    for (int jj = 0; jj < 8; jj++) {
        int p0 = tid + (2 * jj) * 256;
        int p1 = p0 + 256;
        PACK2(px2[jj], X[p0 * 3 + 0], X[p1 * 3 + 0]);
        PACK2(py2[jj], X[p0 * 3 + 1], X[p1 * 3 + 1]);
        PACK2(pz2[jj], X[p0 * 3 + 2], X[p1 * 3 + 2]);
        dm[2 * jj] = 1e10f; dm[2 * jj + 1] = 1e10f;
    }

    __shared__ unsigned long long s_key[2][8];

    int f = 0;                                   // farthest index (block-uniform)
    for (int it = 0; it < S; it++) {
        // uniform-address loads -> one L1 broadcast per component
        const float cx = X[f * 3 + 0], cy = X[f * 3 + 1], cz = X[f * 3 + 2];
        if (tid == 0) g_cent[b * S + it] = make_float4(cx, cy, cz, 0.f);

        unsigned long long ncx2, ncy2, ncz2;
        {
            float nx = -cx, ny = -cy, nz = -cz;
            SPLAT2(ncx2, nx); SPLAT2(ncy2, ny); SPLAT2(ncz2, nz);
        }

        float bv = -1.f;  int bi = 0x7fffffff;
#pragma unroll
        for (int jj = 0; jj < 8; jj++) {
            unsigned long long dx, dy, dz, q0, q1, q2, d2;
            ADD2(dx, px2[jj], ncx2); MUL2(q0, dx, dx);
            ADD2(dy, py2[jj], ncy2); MUL2(q1, dy, dy);
            ADD2(dz, pz2[jj], ncz2); MUL2(q2, dz, dz);
            ADD2(q0, q0, q1);        // (dx*dx + dy*dy)
            ADD2(d2, q0, q2);        // ... + dz*dz
            float d0, d1; UNPACK2(d0, d1, d2);
            float m0 = fminf(dm[2 * jj], d0);     dm[2 * jj] = m0;
            if (m0 > bv) { bv = m0; bi = tid + (2 * jj) * 256; }
            float m1 = fminf(dm[2 * jj + 1], d1); dm[2 * jj + 1] = m1;
            if (m1 > bv) { bv = m1; bi = tid + (2 * jj + 1) * 256; }
        }

        // warp reduce: max value (bits), then min index among holders of the max
        unsigned wv = __reduce_max_sync(0xffffffffu, __float_as_uint(bv));
        unsigned cand = (__float_as_uint(bv) == wv) ? (unsigned)bi : 0x7fffffffu;
        unsigned wbi = __reduce_min_sync(0xffffffffu, cand);

        if (lane == 0)
            s_key[it & 1][wid] =
                ((unsigned long long)wv << 32) | (unsigned long long)(0x7fffffffu - wbi);
        __syncthreads();

        // block reduce: every thread scans the 8 keys (broadcast reads, tree max)
        const unsigned long long* sk = s_key[it & 1];
        unsigned long long b0 = sk[0] > sk[1] ? sk[0] : sk[1];
        unsigned long long b1 = sk[2] > sk[3] ? sk[2] : sk[3];
        unsigned long long b2 = sk[4] > sk[5] ? sk[4] : sk[5];
        unsigned long long b3 = sk[6] > sk[7] ? sk[6] : sk[7];
        b0 = b0 > b1 ? b0 : b1;
        b2 = b2 > b3 ? b2 : b3;
        unsigned long long best = b0 > b2 ? b0 : b2;
        f = (int)(0x7fffffffu - (unsigned)(best & 0xffffffffu));
    }
}

// ---------------- kernel: ball query ----------------
// 512 threads = 16 warps = 16 centroids per block; xyz tile staged in smem (SoA).
__global__ __launch_bounds__(512) void ballq_kernel(const float* __restrict__ xyz) {
    __shared__ float sx[N], sy[N], sz[N];     // 48 KB

    const float R2 = (float)(0.15 * 0.15);    // f64 product cast to f32, matching JAX
    const int tid  = threadIdx.x;
    const int w    = blockIdx.x * 16 + (tid >> 5);
    const int lane = tid & 31;
    const int b    = w >> 10;                 // 64 blocks per batch (16 | 1024)
    const float* X = xyz + (size_t)b * N * 3;

    for (int idx = tid; idx < N * 3; idx += 512) {
        float f = X[idx];
        int p = idx / 3, c = idx - p * 3;
        if (c == 0) sx[p] = f; else if (c == 1) sy[p] = f; else sz[p] = f;
    }
    __syncthreads();

    float4 cc = g_cent[w];
    int count = 0;
    int first = -1;
    int* out = g_gidx + w * NS;

    for (int c0 = 0; c0 < N; c0 += 32) {
        int p = c0 + lane;
        float dx = __fsub_rn(sx[p], cc.x);
        float dy = __fsub_rn(sy[p], cc.y);
        float dz = __fsub_rn(sz[p], cc.z);
        float d = __fadd_rn(__fadd_rn(__fmul_rn(dx, dx), __fmul_rn(dy, dy)),
                            __fmul_rn(dz, dz));
        bool ok = !(d > R2);
        unsigned m = __ballot_sync(0xffffffffu, ok);
        if (count == 0 && m) first = c0 + __ffs(m) - 1;
        int pos = count + __popc(m & ((1u << lane) - 1));
        if (ok && pos < NS) out[pos] = p;
        count += __popc(m);
        if (count >= NS) break;     // warp-uniform (count derived from ballot)
    }
    for (int i = count + lane; i < NS; i += 32) out[i] = first;
}

// ---------------- kernel: fuse weights  Wf = W1@Wc,  bf = b1@Wc + bc ----------
__global__ __launch_bounds__(256) void wfuse_kernel(const float* __restrict__ W1,
                                                    const float* __restrict__ b1,
                                                    const float* __restrict__ Wc,
                                                    const float* __restrict__ bc) {
    __shared__ float sv[CMLP];
    const int i = blockIdx.x;
    const int o = threadIdx.x;
    const float* src = (i < CIN) ? (W1 + i * CMLP) : b1;
    if (o < CMLP) sv[o] = src[o];
    __syncthreads();

    float acc = 0.f;
#pragma unroll 8
    for (int k = 0; k < CMLP; k++) acc += sv[k] * Wc[k * COUT + o];

    if (i < CIN) g_Wf[i * COUT + o] = acc;
    else         g_bf[o] = acc + bc[o];
}

// ---------------- kernel: H = points @ Wf + bf ----------------
// 512 blocks of 64 rows; 256 threads; per-thread 8 rows x 8 cols (f32x2 accs).
__global__ __launch_bounds__(256) void hgemm_kernel(const float* __restrict__ points) {
    __shared__ float Ps[64 * CIN];      // row-major A tile (16 KB)
    __shared__ float Wf[CIN * COUT];    // full fused weight (64 KB)

    const int r0 = blockIdx.x * 64;     // global row over B*N
    const int t  = threadIdx.x;
    const int ty = t >> 5;              // warp id -> row group ty*8 (warp-uniform)
    const int tx = t & 31;              // lane -> col group tx*8

    for (int i = t; i < 64 * CIN; i += 256)
        Ps[i] = points[(size_t)r0 * CIN + i];
    {
        const float4* src = (const float4*)g_Wf;
        float4* dst = (float4*)Wf;
#pragma unroll
        for (int i = 0; i < 16; i++) dst[t + i * 256] = src[t + i * 256];
    }
    __syncthreads();

    unsigned long long acc[8][4];       // [row][colpair]
#pragma unroll
    for (int i = 0; i < 8; i++)
#pragma unroll
        for (int j = 0; j < 4; j++) acc[i][j] = 0ull;

#pragma unroll 4
    for (int k = 0; k < CIN; k++) {
        ulonglong2 wq0 = *(const ulonglong2*)(Wf + k * COUT + tx * 8);
        ulonglong2 wq1 = *(const ulonglong2*)(Wf + k * COUT + tx * 8 + 4);
        unsigned long long wp0 = wq0.x, wp1 = wq0.y, wp2 = wq1.x, wp3 = wq1.y;
#pragma unroll
        for (int ri = 0; ri < 8; ri++) {
            float av = Ps[(ty * 8 + ri) * CIN + k];     // broadcast
            unsigned long long a2; SPLAT2(a2, av);
            FMA2(acc[ri][0], a2, wp0); FMA2(acc[ri][1], a2, wp1);
            FMA2(acc[ri][2], a2, wp2); FMA2(acc[ri][3], a2, wp3);
        }
    }

    float bias[8];
    *(float4*)(bias)     = *(const float4*)(g_bf + tx * 8);
    *(float4*)(bias + 4) = *(const float4*)(g_bf + tx * 8 + 4);

#pragma unroll
    for (int ri = 0; ri < 8; ri++) {
        float v[8];
#pragma unroll
        for (int j = 0; j < 4; j++) {
            float lo, hi; UNPACK2(lo, hi, acc[ri][j]);
            v[2 * j] = lo + bias[2 * j]; v[2 * j + 1] = hi + bias[2 * j + 1];
        }
        float* o = g_H + ((size_t)r0 + ty * 8 + ri) * COUT + tx * 8;
        *(float4*)(o)     = *(float4*)(v);
        *(float4*)(o + 4) = *(float4*)(v + 4);
    }
}

// ---------------- kernel: gather-max pool + BN stats ----------------
__global__ __launch_bounds__(256) void pool_kernel(float* __restrict__ out) {
    __shared__ int rows[NS];
    const int bs = blockIdx.x;
    const int t  = threadIdx.x;
    if (t < NS) rows[t] = g_gidx[bs * NS + t];
    __syncthreads();

    const float* Hb = g_H + ((size_t)(bs >> 10) * N) * COUT + t;   // channel t
    float maxv = -1e30f, sum = 0.f, sq = 0.f;
#pragma unroll 8
    for (int n = 0; n < NS; n++) {
        float v = Hb[(size_t)rows[n] * COUT];
        maxv = fmaxf(maxv, v);
        sum += v;
        sq  += v * v;
    }
    out[(size_t)bs * COUT + t] = maxv;          // raw max(h); normalized in pass 2
    atomicAdd(&g_sum[t], sum);
    atomicAdd(&g_sumsq[t], sq);
}

// ---------------- kernel: BN normalize + relu (in place on d_out) ----------------
__global__ __launch_bounds__(256) void norm_kernel(float* __restrict__ out,
                                                   const float* __restrict__ gamma,
                                                   const float* __restrict__ beta) {
    const int c = threadIdx.x;
    const size_t idx = (size_t)blockIdx.x * COUT + c;
    const float inv_m = 1.f / (float)M_TOT;
    float mean = g_sum[c] * inv_m;
    float var  = g_sumsq[c] * inv_m - mean * mean;
    float rstd = 1.f / sqrtf(var + BN_EPS);
    float h = out[idx];
    float v = (h - mean) * rstd * gamma[c] + beta[c];
    out[idx] = fmaxf(v, 0.f);
}

// ---------------- launch ----------------
extern "C" void kernel_launch(void* const* d_in, const int* in_sizes, int n_in,
                              void* d_out, int out_size) {
    const float* xyz    = (const float*)d_in[0];
    // d_in[1] = t  (unused by the reference)
    const float* points = (const float*)d_in[2];
    const float* W1     = (const float*)d_in[3];
    const float* b1     = (const float*)d_in[4];
    const float* Wc     = (const float*)d_in[5];
    const float* bc     = (const float*)d_in[6];
    const float* gamma  = (const float*)d_in[7];
    const float* beta   = (const float*)d_in[8];
    float* out = (float*)d_out;

    zero_stats_kernel<<<1, 256>>>();
    fps_kernel<<<B, 256>>>(xyz);
    ballq_kernel<<<(B * S) / 16, 512>>>(xyz);
    wfuse_kernel<<<CIN + 1, 256>>>(W1, b1, Wc, bc);
    hgemm_kernel<<<(B * N) / 64, 256>>>(points);
    pool_kernel<<<B * S, 256>>>(out);
    norm_kernel<<<(B * S * COUT) / 256, 256>>>(out, gamma, beta);
}

// round 11
// speedup vs baseline: 2.7733x; 1.0354x over previous
#include <cuda_runtime.h>
#include <cuda_bf16.h>
#include <cstdint>

// ---------------- problem constants ----------------
#define B       8
#define N       4096
#define S       1024          // NPOINT
#define NS      32            // NSAMPLE
#define CIN     64
#define CMLP    128
#define COUT    256
#define BN_EPS  1e-5f
#define M_TOT   (B*S*NS)      // 262144 samples per channel for BN

// ---------------- f32x2 helpers ----------------
#define PACK2(d, lo, hi)   asm("mov.b64 %0, {%1,%2};" : "=l"(d) : "f"(lo), "f"(hi))
#define SPLAT2(d, v)       asm("mov.b64 %0, {%1,%1};" : "=l"(d) : "f"(v))
#define UNPACK2(lo, hi, d) asm("mov.b64 {%0,%1}, %2;" : "=f"(lo), "=f"(hi) : "l"(d))
#define ADD2(o, a, b)      asm("add.rn.f32x2 %0, %1, %2;" : "=l"(o) : "l"(a), "l"(b))
#define MUL2(o, a, b)      asm("mul.rn.f32x2 %0, %1, %2;" : "=l"(o) : "l"(a), "l"(b))
#define FMA2(acc, a, b)    asm("fma.rn.f32x2 %0, %1, %2, %0;" : "+l"(acc) : "l"(a), "l"(b))

// ---------------- device scratch (no allocs allowed) ----------------
__device__ float4 g_cent[B * S];                     // FPS centroids (new_xyz)
__device__ int    g_gidx[B * S * NS];                // ball query indices (1 MB)
__device__ float  g_Wf[CIN * COUT];                  // fused W1@Wc   (64x256)
__device__ float  g_bf[COUT];                        // fused b1@Wc + bc
__device__ float  g_H[(size_t)B * N * COUT];         // points@Wf + bf  (33.5 MB)
__device__ float  g_sum[COUT];
__device__ float  g_sumsq[COUT];

// ---------------- kernel: farthest point sampling ----------------
// 256 threads (8 warps), 16 points/thread as 8 f32x2 pairs, REDUX +
// single-barrier u64-key block reduce (all as in the passing round-10 kernel).
// NEW: per-thread argmax runs as 4 INDEPENDENT chains (chain c = jj>>1) merged
// by a 3-node tree, cutting the serial (bv,bi) dependency depth 16 -> ~6.
// Tie-exactness: chain c owns the contiguous ascending index range
// tid + [c*1024, c*1024+768], so every chain-c index < every chain-(c+1)
// index; merging with strict > (lower chain wins ties) and in-chain strict >
// in ascending index order reproduces (max value, lowest index) exactly.
__global__ __launch_bounds__(256) void fps_kernel(const float* __restrict__ xyz) {
    const int b = blockIdx.x;
    const float* X = xyz + (size_t)b * N * 3;
    const int tid = threadIdx.x;
    const int lane = tid & 31, wid = tid >> 5;

    unsigned long long px2[8], py2[8], pz2[8];
    float dm[16];
#pragma unroll
    for (int jj = 0; jj < 8; jj++) {
        int p0 = tid + (2 * jj) * 256;
        int p1 = p0 + 256;
        PACK2(px2[jj], X[p0 * 3 + 0], X[p1 * 3 + 0]);
        PACK2(py2[jj], X[p0 * 3 + 1], X[p1 * 3 + 1]);
        PACK2(pz2[jj], X[p0 * 3 + 2], X[p1 * 3 + 2]);
        dm[2 * jj] = 1e10f; dm[2 * jj + 1] = 1e10f;
    }

    __shared__ unsigned long long s_key[2][8];

    int f = 0;                                   // farthest index (block-uniform)
    for (int it = 0; it < S; it++) {
        // uniform-address loads -> one L1 broadcast per component
        const float cx = X[f * 3 + 0], cy = X[f * 3 + 1], cz = X[f * 3 + 2];
        if (tid == 0) g_cent[b * S + it] = make_float4(cx, cy, cz, 0.f);

        unsigned long long ncx2, ncy2, ncz2;
        {
            float nx = -cx, ny = -cy, nz = -cz;
            SPLAT2(ncx2, nx); SPLAT2(ncy2, ny); SPLAT2(ncz2, nz);
        }

        float bv[4];  int bix[4];
#pragma unroll
        for (int c = 0; c < 4; c++) { bv[c] = -1.f; bix[c] = 0x7fffffff; }

#pragma unroll
        for (int jj = 0; jj < 8; jj++) {
            const int c = jj >> 1;               // chain id (contiguous idx range)
            unsigned long long dx, dy, dz, q0, q1, q2, d2;
            ADD2(dx, px2[jj], ncx2); MUL2(q0, dx, dx);
            ADD2(dy, py2[jj], ncy2); MUL2(q1, dy, dy);
            ADD2(dz, pz2[jj], ncz2); MUL2(q2, dz, dz);
            ADD2(q0, q0, q1);        // (dx*dx + dy*dy)
            ADD2(d2, q0, q2);        // ... + dz*dz
            float d0, d1; UNPACK2(d0, d1, d2);
            float m0 = fminf(dm[2 * jj], d0);     dm[2 * jj] = m0;
            if (m0 > bv[c]) { bv[c] = m0; bix[c] = tid + (2 * jj) * 256; }
            float m1 = fminf(dm[2 * jj + 1], d1); dm[2 * jj + 1] = m1;
            if (m1 > bv[c]) { bv[c] = m1; bix[c] = tid + (2 * jj + 1) * 256; }
        }
        // merge tree: strict > so the lower chain (lower indices) wins ties
        float v01 = bv[1] > bv[0] ? bv[1] : bv[0];
        int   i01 = bv[1] > bv[0] ? bix[1] : bix[0];
        float v23 = bv[3] > bv[2] ? bv[3] : bv[2];
        int   i23 = bv[3] > bv[2] ? bix[3] : bix[2];
        bool  tmx = v23 > v01;
        float bvf = tmx ? v23 : v01;
        int   bif = tmx ? i23 : i01;

        // warp reduce: max value (bits), then min index among holders of the max
        unsigned wv = __reduce_max_sync(0xffffffffu, __float_as_uint(bvf));
        unsigned cand = (__float_as_uint(bvf) == wv) ? (unsigned)bif : 0x7fffffffu;
        unsigned wbi = __reduce_min_sync(0xffffffffu, cand);

        if (lane == 0)
            s_key[it & 1][wid] =
                ((unsigned long long)wv << 32) | (unsigned long long)(0x7fffffffu - wbi);
        __syncthreads();

        // block reduce: every thread scans the 8 keys (broadcast reads, tree max)
        const unsigned long long* sk = s_key[it & 1];
        unsigned long long b0 = sk[0] > sk[1] ? sk[0] : sk[1];
        unsigned long long b1 = sk[2] > sk[3] ? sk[2] : sk[3];
        unsigned long long b2 = sk[4] > sk[5] ? sk[4] : sk[5];
        unsigned long long b3 = sk[6] > sk[7] ? sk[6] : sk[7];
        b0 = b0 > b1 ? b0 : b1;
        b2 = b2 > b3 ? b2 : b3;
        unsigned long long best = b0 > b2 ? b0 : b2;
        f = (int)(0x7fffffffu - (unsigned)(best & 0xffffffffu));
    }
}

// ---------------- kernel: ball query ----------------
// 512 threads = 16 warps = 16 centroids per block; xyz tile staged in smem (SoA).
__global__ __launch_bounds__(512) void ballq_kernel(const float* __restrict__ xyz) {
    __shared__ float sx[N], sy[N], sz[N];     // 48 KB

    const float R2 = (float)(0.15 * 0.15);    // f64 product cast to f32, matching JAX
    const int tid  = threadIdx.x;
    const int w    = blockIdx.x * 16 + (tid >> 5);
    const int lane = tid & 31;
    const int b    = w >> 10;                 // 64 blocks per batch (16 | 1024)
    const float* X = xyz + (size_t)b * N * 3;

    for (int idx = tid; idx < N * 3; idx += 512) {
        float f = X[idx];
        int p = idx / 3, c = idx - p * 3;
        if (c == 0) sx[p] = f; else if (c == 1) sy[p] = f; else sz[p] = f;
    }
    __syncthreads();

    float4 cc = g_cent[w];
    int count = 0;
    int first = -1;
    int* out = g_gidx + w * NS;

    for (int c0 = 0; c0 < N; c0 += 32) {
        int p = c0 + lane;
        float dx = __fsub_rn(sx[p], cc.x);
        float dy = __fsub_rn(sy[p], cc.y);
        float dz = __fsub_rn(sz[p], cc.z);
        float d = __fadd_rn(__fadd_rn(__fmul_rn(dx, dx), __fmul_rn(dy, dy)),
                            __fmul_rn(dz, dz));
        bool ok = !(d > R2);
        unsigned m = __ballot_sync(0xffffffffu, ok);
        if (count == 0 && m) first = c0 + __ffs(m) - 1;
        int pos = count + __popc(m & ((1u << lane) - 1));
        if (ok && pos < NS) out[pos] = p;
        count += __popc(m);
        if (count >= NS) break;     // warp-uniform (count derived from ballot)
    }
    for (int i = count + lane; i < NS; i += 32) out[i] = first;
}

// ---------------- kernel: fuse weights  Wf = W1@Wc,  bf = b1@Wc + bc ----------
// blocks 0..63 -> row i of W1; block 64 -> b1 row (+bc) AND zeroes BN stats.
__global__ __launch_bounds__(256) void wfuse_kernel(const float* __restrict__ W1,
                                                    const float* __restrict__ b1,
                                                    const float* __restrict__ Wc,
                                                    const float* __restrict__ bc) {
    __shared__ float sv[CMLP];
    const int i = blockIdx.x;
    const int o = threadIdx.x;
    const float* src = (i < CIN) ? (W1 + i * CMLP) : b1;
    if (o < CMLP) sv[o] = src[o];
    __syncthreads();

    float acc = 0.f;
#pragma unroll 8
    for (int k = 0; k < CMLP; k++) acc += sv[k] * Wc[k * COUT + o];

    if (i < CIN) {
        g_Wf[i * COUT + o] = acc;
    } else {
        g_bf[o] = acc + bc[o];
        g_sum[o] = 0.f;                       // folded zero_stats
        g_sumsq[o] = 0.f;
    }
}

// ---------------- kernel: H = points @ Wf + bf ----------------
// 512 blocks of 64 rows; 256 threads; per-thread 8 rows x 8 cols (f32x2 accs).
__global__ __launch_bounds__(256) void hgemm_kernel(const float* __restrict__ points) {
    __shared__ float Ps[64 * CIN];      // row-major A tile (16 KB)
    __shared__ float Wf[CIN * COUT];    // full fused weight (64 KB)

    const int r0 = blockIdx.x * 64;     // global row over B*N
    const int t  = threadIdx.x;
    const int ty = t >> 5;              // warp id -> row group ty*8 (warp-uniform)
    const int tx = t & 31;              // lane -> col group tx*8

    for (int i = t; i < 64 * CIN; i += 256)
        Ps[i] = points[(size_t)r0 * CIN + i];
    {
        const float4* src = (const float4*)g_Wf;
        float4* dst = (float4*)Wf;
#pragma unroll
        for (int i = 0; i < 16; i++) dst[t + i * 256] = src[t + i * 256];
    }
    __syncthreads();

    unsigned long long acc[8][4];       // [row][colpair]
#pragma unroll
    for (int i = 0; i < 8; i++)
#pragma unroll
        for (int j = 0; j < 4; j++) acc[i][j] = 0ull;

#pragma unroll 4
    for (int k = 0; k < CIN; k++) {
        ulonglong2 wq0 = *(const ulonglong2*)(Wf + k * COUT + tx * 8);
        ulonglong2 wq1 = *(const ulonglong2*)(Wf + k * COUT + tx * 8 + 4);
        unsigned long long wp0 = wq0.x, wp1 = wq0.y, wp2 = wq1.x, wp3 = wq1.y;
#pragma unroll
        for (int ri = 0; ri < 8; ri++) {
            float av = Ps[(ty * 8 + ri) * CIN + k];     // broadcast
            unsigned long long a2; SPLAT2(a2, av);
            FMA2(acc[ri][0], a2, wp0); FMA2(acc[ri][1], a2, wp1);
            FMA2(acc[ri][2], a2, wp2); FMA2(acc[ri][3], a2, wp3);
        }
    }

    float bias[8];
    *(float4*)(bias)     = *(const float4*)(g_bf + tx * 8);
    *(float4*)(bias + 4) = *(const float4*)(g_bf + tx * 8 + 4);

#pragma unroll
    for (int ri = 0; ri < 8; ri++) {
        float v[8];
#pragma unroll
        for (int j = 0; j < 4; j++) {
            float lo, hi; UNPACK2(lo, hi, acc[ri][j]);
            v[2 * j] = lo + bias[2 * j]; v[2 * j + 1] = hi + bias[2 * j + 1];
        }
        float* o = g_H + ((size_t)r0 + ty * 8 + ri) * COUT + tx * 8;
        *(float4*)(o)     = *(float4*)(v);
        *(float4*)(o + 4) = *(float4*)(v + 4);
    }
}

// ---------------- kernel: gather-max pool + BN stats ----------------
__global__ __launch_bounds__(256) void pool_kernel(float* __restrict__ out) {
    __shared__ int rows[NS];
    const int bs = blockIdx.x;
    const int t  = threadIdx.x;
    if (t < NS) rows[t] = g_gidx[bs * NS + t];
    __syncthreads();

    const float* Hb = g_H + ((size_t)(bs >> 10) * N) * COUT + t;   // channel t
    float maxv = -1e30f, sum = 0.f, sq = 0.f;
#pragma unroll 8
    for (int n = 0; n < NS; n++) {
        float v = Hb[(size_t)rows[n] * COUT];
        maxv = fmaxf(maxv, v);
        sum += v;
        sq  += v * v;
    }
    out[(size_t)bs * COUT + t] = maxv;          // raw max(h); normalized in pass 2
    atomicAdd(&g_sum[t], sum);
    atomicAdd(&g_sumsq[t], sq);
}

// ---------------- kernel: BN normalize + relu (in place on d_out) ----------------
__global__ __launch_bounds__(256) void norm_kernel(float* __restrict__ out,
                                                   const float* __restrict__ gamma,
                                                   const float* __restrict__ beta) {
    const int c = threadIdx.x;
    const size_t idx = (size_t)blockIdx.x * COUT + c;
    const float inv_m = 1.f / (float)M_TOT;
    float mean = g_sum[c] * inv_m;
    float var  = g_sumsq[c] * inv_m - mean * mean;
    float rstd = 1.f / sqrtf(var + BN_EPS);
    float h = out[idx];
    float v = (h - mean) * rstd * gamma[c] + beta[c];
    out[idx] = fmaxf(v, 0.f);
}

// ---------------- launch ----------------
extern "C" void kernel_launch(void* const* d_in, const int* in_sizes, int n_in,
                              void* d_out, int out_size) {
    const float* xyz    = (const float*)d_in[0];
    // d_in[1] = t  (unused by the reference)
    const float* points = (const float*)d_in[2];
    const float* W1     = (const float*)d_in[3];
    const float* b1     = (const float*)d_in[4];
    const float* Wc     = (const float*)d_in[5];
    const float* bc     = (const float*)d_in[6];
    const float* gamma  = (const float*)d_in[7];
    const float* beta   = (const float*)d_in[8];
    float* out = (float*)d_out;

    fps_kernel<<<B, 256>>>(xyz);
    ballq_kernel<<<(B * S) / 16, 512>>>(xyz);
    wfuse_kernel<<<CIN + 1, 256>>>(W1, b1, Wc, bc);
    hgemm_kernel<<<(B * N) / 64, 256>>>(points);
    pool_kernel<<<B * S, 256>>>(out);
    norm_kernel<<<(B * S * COUT) / 256, 256>>>(out, gamma, beta);
}